// round 1
// baseline (speedup 1.0000x reference)
#include <cuda_runtime.h>
#include <math.h>

// Problem constants (fixed by the reference's setup_inputs)
#define Bc 2
#define Vc 3
#define Cc 32
#define Dc 32
#define Hc 96
#define Wc 128
#define HWc (Hc * Wc)            // 12288
#define VOLc (Bc * Dc * Hc * Wc) // 786432
#define BHWc (Bc * Hc * Wc)      // 24576
#define NSRC (Vc - 1)            // 2 source views

// Scratch (static device globals — no allocation)
__device__ float g_u[27 * VOLc];          // channel-contracted 27-tap partials (~85 MB)
__device__ float g_pre[VOLc];             // conv output (3 MB)
__device__ float g_xform[Bc * NSRC * 12]; // rot(9) + trans(3) per (b, src view)

// ---------------------------------------------------------------------------
// Setup: compose projections, invert ref, proj = src @ inv(ref)
// ---------------------------------------------------------------------------
__device__ void compose_mat(const float* pm, int b, int v, float P[16]) {
    const float* E = pm + (((b * Vc + v) * 2 + 0) * 16);
    const float* K = pm + (((b * Vc + v) * 2 + 1) * 16);
#pragma unroll
    for (int i = 0; i < 16; i++) P[i] = E[i];
#pragma unroll
    for (int i = 0; i < 3; i++)
#pragma unroll
        for (int j = 0; j < 4; j++)
            P[i * 4 + j] = K[i * 4 + 0] * E[0 * 4 + j] +
                           K[i * 4 + 1] * E[1 * 4 + j] +
                           K[i * 4 + 2] * E[2 * 4 + j];
}

__device__ void inv4(const float A[16], float R[16]) {
    float M[4][8];
    for (int i = 0; i < 4; i++) {
        for (int j = 0; j < 4; j++) {
            M[i][j] = A[i * 4 + j];
            M[i][4 + j] = (i == j) ? 1.f : 0.f;
        }
    }
    for (int col = 0; col < 4; col++) {
        int piv = col;
        float best = fabsf(M[col][col]);
        for (int r = col + 1; r < 4; r++) {
            float a = fabsf(M[r][col]);
            if (a > best) { best = a; piv = r; }
        }
        if (piv != col) {
            for (int j = 0; j < 8; j++) {
                float t = M[col][j]; M[col][j] = M[piv][j]; M[piv][j] = t;
            }
        }
        float p = 1.f / M[col][col];
        for (int j = 0; j < 8; j++) M[col][j] *= p;
        for (int r = 0; r < 4; r++) {
            if (r == col) continue;
            float f = M[r][col];
            for (int j = 0; j < 8; j++) M[r][j] -= f * M[col][j];
        }
    }
    for (int i = 0; i < 4; i++)
        for (int j = 0; j < 4; j++)
            R[i * 4 + j] = M[i][4 + j];
}

__global__ void setup_kernel(const float* __restrict__ pm) {
    int t = threadIdx.x;
    if (t >= Bc * NSRC) return;
    int b = t / NSRC;
    int v = (t % NSRC) + 1;
    float refP[16], srcP[16], invR[16], proj[16];
    compose_mat(pm, b, 0, refP);
    compose_mat(pm, b, v, srcP);
    inv4(refP, invR);
    for (int i = 0; i < 4; i++)
        for (int j = 0; j < 4; j++) {
            float s = 0.f;
            for (int k = 0; k < 4; k++) s += srcP[i * 4 + k] * invR[k * 4 + j];
            proj[i * 4 + j] = s;
        }
    float* X = g_xform + t * 12;
    X[0] = proj[0];  X[1] = proj[1];  X[2] = proj[2];
    X[3] = proj[4];  X[4] = proj[5];  X[5] = proj[6];
    X[6] = proj[8];  X[7] = proj[9];  X[8] = proj[10];
    X[9] = proj[3];  X[10] = proj[7]; X[11] = proj[11];
}

// ---------------------------------------------------------------------------
// build_u: per-voxel warp + variance + channel contraction with w_reg
// ---------------------------------------------------------------------------
__global__ __launch_bounds__(256) void build_u_kernel(
    const float* __restrict__ features,
    const float* __restrict__ depth_values,
    const float* __restrict__ w_reg)
{
    __shared__ float sw[Cc * 28]; // per-channel 27 weights, padded to 28 (16B aligned rows)
    int tid = threadIdx.x;
    for (int i = tid; i < Cc * 28; i += 256) {
        int c = i / 28, t = i % 28;
        sw[i] = (t < 27) ? w_reg[c * 27 + t] : 0.f;
    }
    __syncthreads();

    int idx = blockIdx.x * 256 + tid; // linear over (b,d,h,w)
    int w = idx & (Wc - 1);
    int h = (idx / Wc) % Hc;
    int b = idx / (Dc * HWc);

    float depth = depth_values[idx]; // (B,D,H,W) matches linear idx

    float wt[NSRC][4];
    int off[NSRC][4];
#pragma unroll
    for (int s = 0; s < NSRC; s++) {
        const float* X = g_xform + (b * NSRC + s) * 12;
        float fx = (float)w, fy = (float)h;
        float Xx = (X[0] * fx + X[1] * fy + X[2]) * depth + X[9];
        float Yy = (X[3] * fx + X[4] * fy + X[5]) * depth + X[10];
        float Zz = (X[6] * fx + X[7] * fy + X[8]) * depth + X[11];
        float iz = 1.f / Zz;
        float px = Xx * iz, py = Yy * iz;
        float x0 = floorf(px), y0 = floorf(py);
        float ax = px - x0, ay = py - y0;
#pragma unroll
        for (int k = 0; k < 4; k++) {
            int dx = k & 1, dy = k >> 1;
            float xi = x0 + (float)dx, yi = y0 + (float)dy;
            float wg = (dx ? ax : 1.f - ax) * (dy ? ay : 1.f - ay);
            bool valid = (xi >= 0.f) && (xi <= (float)(Wc - 1)) &&
                         (yi >= 0.f) && (yi <= (float)(Hc - 1));
            wt[s][k] = valid ? wg : 0.f;
            int xc = min(max((int)xi, 0), Wc - 1);
            int yc = min(max((int)yi, 0), Hc - 1);
            off[s][k] = yc * Wc + xc;
        }
    }

    float u[27];
#pragma unroll
    for (int t = 0; t < 27; t++) u[t] = 0.f;

    int pix = h * Wc + w;
    const float* fref = features + (size_t)(b * Vc + 0) * (Cc * HWc) + pix;
    const float* f1 = features + (size_t)(b * Vc + 1) * (Cc * HWc);
    const float* f2 = features + (size_t)(b * Vc + 2) * (Cc * HWc);

    const float inv3 = 1.f / 3.f;
    for (int c = 0; c < Cc; c++) {
        float r = __ldg(fref + c * HWc);
        const float* p1 = f1 + c * HWc;
        float v1 = wt[0][0] * __ldg(p1 + off[0][0]) + wt[0][1] * __ldg(p1 + off[0][1]) +
                   wt[0][2] * __ldg(p1 + off[0][2]) + wt[0][3] * __ldg(p1 + off[0][3]);
        const float* p2 = f2 + c * HWc;
        float v2 = wt[1][0] * __ldg(p2 + off[1][0]) + wt[1][1] * __ldg(p2 + off[1][1]) +
                   wt[1][2] * __ldg(p2 + off[1][2]) + wt[1][3] * __ldg(p2 + off[1][3]);
        float s = r + v1 + v2;
        float q = r * r + v1 * v1 + v2 * v2;
        float m = s * inv3;
        float var = q * inv3 - m * m;

        const float4* wr = (const float4*)(sw + c * 28);
        float4 a;
        a = wr[0]; u[0] += var * a.x;  u[1] += var * a.y;  u[2] += var * a.z;  u[3] += var * a.w;
        a = wr[1]; u[4] += var * a.x;  u[5] += var * a.y;  u[6] += var * a.z;  u[7] += var * a.w;
        a = wr[2]; u[8] += var * a.x;  u[9] += var * a.y;  u[10] += var * a.z; u[11] += var * a.w;
        a = wr[3]; u[12] += var * a.x; u[13] += var * a.y; u[14] += var * a.z; u[15] += var * a.w;
        a = wr[4]; u[16] += var * a.x; u[17] += var * a.y; u[18] += var * a.z; u[19] += var * a.w;
        a = wr[5]; u[20] += var * a.x; u[21] += var * a.y; u[22] += var * a.z; u[23] += var * a.w;
        a = wr[6]; u[24] += var * a.x; u[25] += var * a.y; u[26] += var * a.z;
    }

#pragma unroll
    for (int t = 0; t < 27; t++) g_u[t * VOLc + idx] = u[t];
}

// ---------------------------------------------------------------------------
// conv: pre(p) = bias + sum_t u_t(p + delta_t - 1)  (zero amplification)
// ---------------------------------------------------------------------------
__global__ __launch_bounds__(256) void conv_kernel(const float* __restrict__ breg) {
    int idx = blockIdx.x * 256 + threadIdx.x;
    int w = idx & (Wc - 1);
    int h = (idx / Wc) % Hc;
    int d = (idx / HWc) % Dc;

    float acc = breg[0];
#pragma unroll
    for (int dz = 0; dz < 3; dz++) {
        int zz = d + dz - 1;
        if (zz < 0 || zz >= Dc) continue;
#pragma unroll
        for (int dy = 0; dy < 3; dy++) {
            int yy = h + dy - 1;
            if (yy < 0 || yy >= Hc) continue;
#pragma unroll
            for (int dx = 0; dx < 3; dx++) {
                int xx = w + dx - 1;
                if (xx < 0 || xx >= Wc) continue;
                int t = dz * 9 + dy * 3 + dx;
                int nb = idx + (dz - 1) * HWc + (dy - 1) * Wc + (dx - 1);
                acc += g_u[t * VOLc + nb];
            }
        }
    }
    g_pre[idx] = acc;
}

// ---------------------------------------------------------------------------
// finalize: softmax over D, expected depth, 4-window confidence
// ---------------------------------------------------------------------------
__global__ __launch_bounds__(256) void finalize_kernel(
    const float* __restrict__ depth_values, float* __restrict__ out)
{
    int idx = blockIdx.x * 256 + threadIdx.x; // linear over (b,h,w)
    if (idx >= BHWc) return;
    int w = idx & (Wc - 1);
    int h = (idx / Wc) % Hc;
    int b = idx / HWc;
    int base = b * (Dc * HWc) + h * Wc + w;

    float p[Dc];
    float mx = -3.0e38f;
#pragma unroll
    for (int d = 0; d < Dc; d++) {
        p[d] = g_pre[base + d * HWc];
        mx = fmaxf(mx, p[d]);
    }
    float ssum = 0.f;
#pragma unroll
    for (int d = 0; d < Dc; d++) {
        p[d] = __expf(p[d] - mx);
        ssum += p[d];
    }
    float inv = 1.f / ssum;
    float depth = 0.f, ed = 0.f;
#pragma unroll
    for (int d = 0; d < Dc; d++) {
        float pd = p[d] * inv;
        p[d] = pd;
        depth += pd * depth_values[base + d * HWc];
        ed += pd * (float)d;
    }
    int ix = (int)ed;             // ed >= 0, truncation == reference astype
    ix = min(max(ix, 0), Dc - 1);
    float conf = 0.f;
#pragma unroll
    for (int d = 0; d < Dc; d++)
        conf += (d >= ix - 1 && d <= ix + 2) ? p[d] : 0.f;

    out[idx] = depth;
    out[BHWc + idx] = conf;
}

// ---------------------------------------------------------------------------
extern "C" void kernel_launch(void* const* d_in, const int* in_sizes, int n_in,
                              void* d_out, int out_size)
{
    // Identify inputs by element count (robust to ordering):
    // features=2359296, depth_values=786432, proj=192, w_reg=864, b_reg=1
    const float* features = nullptr;
    const float* projm = nullptr;
    const float* depthv = nullptr;
    const float* wreg = nullptr;
    const float* breg = nullptr;
    for (int i = 0; i < n_in; i++) {
        switch (in_sizes[i]) {
            case Bc * Vc * Cc * HWc: features = (const float*)d_in[i]; break;
            case VOLc:               depthv = (const float*)d_in[i]; break;
            case Bc * Vc * 2 * 16:   projm = (const float*)d_in[i]; break;
            case Cc * 27:            wreg = (const float*)d_in[i]; break;
            case 1:                  breg = (const float*)d_in[i]; break;
            default: break;
        }
    }
    float* out = (float*)d_out;

    setup_kernel<<<1, 32>>>(projm);
    build_u_kernel<<<VOLc / 256, 256>>>(features, depthv, wreg);
    conv_kernel<<<VOLc / 256, 256>>>(breg);
    finalize_kernel<<<BHWc / 256, 256>>>(depthv, out);
}